// round 14
// baseline (speedup 1.0000x reference)
#include <cuda_runtime.h>
#include <cuda_fp16.h>
#include <cstdint>

#define B_DIM 8192
#define I_DIM 512
#define C_DIM 2048

#define BM 128
#define BN 128
#define BK 32                        // K-slice of x per iteration
#define NITER (I_DIM / BK)           // 16
#define NSTAGE 3
#define PITCH 40                     // halves per smem row (32 + 8 pad) = 80 B (16B-aligned)
#define REGION_BYTES (BM * PITCH * 2)        // 10240 (one operand tile)
#define STAGE_BYTES (3 * REGION_BYTES)       // 30720 (A + B1 + B2)
#define SMEM_BYTES (NSTAGE * STAGE_BYTES)    // 92160

// ---------------- device scratch (no allocs allowed) ----------------
__device__ __half g_a [B_DIM * I_DIM];   // h(x)                    (8192, 512)
__device__ __half g_bt[C_DIM * 1024];    // [h(w^2) | h(-2 w^2 c)]  (2048, 1024)
__device__ float  g_t3p[16 * C_DIM];
__device__ float  g_t3[C_DIM];

// ---------------- helpers ----------------
__device__ __forceinline__ uint32_t smem_u32(const void* p) {
    uint32_t a;
    asm("{ .reg .u64 t; cvta.to.shared.u64 t, %1; cvt.u32.u64 %0, t; }" : "=r"(a) : "l"(p));
    return a;
}
__device__ __forceinline__ void cp_async16(uint32_t saddr, const void* gaddr) {
    asm volatile("cp.async.cg.shared.global [%0], [%1], 16;" :: "r"(saddr), "l"(gaddr));
}
__device__ __forceinline__ void cp_commit() {
    asm volatile("cp.async.commit_group;" ::: "memory");
}
__device__ __forceinline__ void cp_wait1() {
    asm volatile("cp.async.wait_group 1;" ::: "memory");
}
__device__ __forceinline__ void cp_wait0() {
    asm volatile("cp.async.wait_group 0;" ::: "memory");
}
__device__ __forceinline__ void ldsm_x4(uint32_t* r, uint32_t addr) {
    asm volatile("ldmatrix.sync.aligned.m8n8.x4.shared.b16 {%0,%1,%2,%3}, [%4];"
                 : "=r"(r[0]), "=r"(r[1]), "=r"(r[2]), "=r"(r[3]) : "r"(addr));
}
__device__ __forceinline__ uint32_t h2sq(uint32_t v) {
    uint32_t r; asm("mul.rn.f16x2 %0, %1, %1;" : "=r"(r) : "r"(v)); return r;
}
__device__ __forceinline__ void mma_f16(float* d, const uint32_t* a, uint32_t b0, uint32_t b1) {
    asm volatile(
        "mma.sync.aligned.m16n8k16.row.col.f32.f16.f16.f32 "
        "{%0,%1,%2,%3}, {%4,%5,%6,%7}, {%8,%9}, {%0,%1,%2,%3};"
        : "+f"(d[0]), "+f"(d[1]), "+f"(d[2]), "+f"(d[3])
        : "r"(a[0]), "r"(a[1]), "r"(a[2]), "r"(a[3]), "r"(b0), "r"(b1));
}

// ---------------------------------------------------------------------------
// prep_w: g_bt[c] = [h(w^2) | h(-2 w^2 centers)], + fp32 t3 partials.
// ---------------------------------------------------------------------------
__global__ void prep_w_kernel(const float* __restrict__ weight,
                              const float* __restrict__ centers) {
    __shared__ float sW[32][33];
    __shared__ float sC[32][33];

    const int i0 = blockIdx.x * 32;
    const int c0 = blockIdx.y * 32;
    const int tx = threadIdx.x;
    const int ty = threadIdx.y;

    #pragma unroll
    for (int ii = ty; ii < 32; ii += 8)
        sW[ii][tx] = weight[(i0 + ii) * C_DIM + c0 + tx];
    #pragma unroll
    for (int cc = ty; cc < 32; cc += 8)
        sC[cc][tx] = centers[(c0 + cc) * I_DIM + i0 + tx];
    __syncthreads();

    #pragma unroll
    for (int cc = ty; cc < 32; cc += 8) {
        float w  = sW[tx][cc];
        float w2 = w * w;
        float ce = sC[cc][tx];
        __half* row = g_bt + (size_t)(c0 + cc) * 1024;
        row[i0 + tx]         = __float2half_rn(w2);
        row[I_DIM + i0 + tx] = __float2half_rn(-2.0f * w2 * ce);
        float v = w2 * ce * ce;
        #pragma unroll
        for (int d = 16; d > 0; d >>= 1)
            v += __shfl_xor_sync(0xFFFFFFFF, v, d);
        if (tx == 0) g_t3p[blockIdx.x * C_DIM + c0 + cc] = v;
    }
}

__global__ void t3_reduce_kernel() {
    int c = blockIdx.x * blockDim.x + threadIdx.x;
    if (c < C_DIM) {
        float s = 0.0f;
        #pragma unroll
        for (int p = 0; p < 16; p++) s += g_t3p[p * C_DIM + c];
        g_t3[c] = s;
    }
}

// ---------------------------------------------------------------------------
// prep_x: g_a = h(x) only (x^2 is formed in registers inside the GEMM).
// ---------------------------------------------------------------------------
__global__ void prep_x_kernel(const float* __restrict__ x) {
    int f = blockIdx.x * blockDim.x + threadIdx.x;   // float4 id, [0, 1M)
    int r  = f >> 7;
    int c4 = (f & 127) << 2;
    float4 v = *reinterpret_cast<const float4*>(x + (size_t)r * I_DIM + c4);
    __half2 rw0 = __floats2half2_rn(v.x, v.y);
    __half2 rw1 = __floats2half2_rn(v.z, v.w);
    __half2* pa = reinterpret_cast<__half2*>(g_a + (size_t)r * I_DIM + c4);
    pa[0] = rw0; pa[1] = rw1;
}

// ---------------------------------------------------------------------------
// GEMM: out[b,c] = sum_k x^2 B1 + x B2 + t3, K=512, x^2 formed in registers.
// 128x128x32 iter tile, 3-stage cp.async, 8 warps (4m x 2n), warp tile
// 32x64, m16n8k16 f16/fp32, 1 barrier per iteration.
// ---------------------------------------------------------------------------
__global__ __launch_bounds__(256, 2)
void rbf_mma_gemm(float* __restrict__ out) {
    extern __shared__ char smem[];
    const uint32_t sbase = smem_u32(smem);

    const int tid = threadIdx.x;
    const int wid = tid >> 5;
    const int lid = tid & 31;
    const int g   = lid >> 2;
    const int tg  = lid & 3;
    const int wm  = wid >> 1;       // 0..3 -> m offset wm*32
    const int wn  = wid & 1;        // 0..1 -> n offset wn*64

    const int block_row = blockIdx.y * BM;
    const int block_col = blockIdx.x * BN;
    const __half* gA = g_a  + (size_t)block_row * I_DIM;
    const __half* gB = g_bt + (size_t)block_col * 1024;

    // cp.async: per stage, per operand, 512 x 16B chunks; 256 thr x 2.
    // 4 threads/row, lanes 0-3 cover 64B contiguous.
    auto prefetch = [&](int it) {
        const int s  = it % NSTAGE;
        const int k0 = it * BK;
        const uint32_t sa = sbase + s * STAGE_BYTES;
        #pragma unroll
        for (int i = 0; i < 2; i++) {
            const int f   = tid + i * 256;     // [0, 512)
            const int row = f >> 2;            // 0..127
            const int kc  = (f & 3) << 3;      // 0,8,16,24 halves
            const uint32_t soff = (uint32_t)(row * PITCH + kc) * 2;
            cp_async16(sa + soff,
                       gA + (size_t)row * I_DIM + k0 + kc);
            cp_async16(sa + REGION_BYTES + soff,
                       gB + (size_t)row * 1024 + k0 + kc);
            cp_async16(sa + 2 * REGION_BYTES + soff,
                       gB + (size_t)row * 1024 + I_DIM + k0 + kc);
        }
    };

    // ldmatrix per-lane address components
    const int a_row = (lid & 15);
    const int a_kh  = (lid >> 4) << 3;
    const int b_row = (lid & 7) + ((lid & 16) >> 1);
    const int b_kh  = (lid & 8);
    const uint32_t a_lane_off = ((uint32_t)(wm * 32 + a_row) * PITCH + a_kh) * 2;
    const uint32_t b_lane_off = ((uint32_t)(wn * 64 + b_row) * PITCH + b_kh) * 2;

    float acc[2][8][4];
    #pragma unroll
    for (int mf = 0; mf < 2; mf++)
        #pragma unroll
        for (int nf = 0; nf < 8; nf++)
            #pragma unroll
            for (int e = 0; e < 4; e++) acc[mf][nf][e] = 0.0f;

    prefetch(0); cp_commit();
    prefetch(1); cp_commit();

    for (int it = 0; it < NITER; it++) {
        if (it == NITER - 1) cp_wait0(); else cp_wait1();
        __syncthreads();
        if (it + 2 < NITER) { prefetch(it + 2); cp_commit(); }

        const uint32_t stageBase = sbase + (it % NSTAGE) * STAGE_BYTES;
        const uint32_t aBase  = stageBase + a_lane_off;
        const uint32_t b1Base = stageBase + REGION_BYTES + b_lane_off;
        const uint32_t b2Base = stageBase + 2 * REGION_BYTES + b_lane_off;

        #pragma unroll
        for (int kf = 0; kf < 2; kf++) {           // BK=32 -> 2 k16 slices
            const uint32_t koff = (uint32_t)(kf * 16) * 2;

            uint32_t af[2][4], aq[2][4];
            #pragma unroll
            for (int mf = 0; mf < 2; mf++) {
                ldsm_x4(af[mf], aBase + (uint32_t)(mf * 16 * PITCH) * 2 + koff);
                #pragma unroll
                for (int e = 0; e < 4; e++) aq[mf][e] = h2sq(af[mf][e]);
            }

            #pragma unroll
            for (int np = 0; np < 4; np++) {
                uint32_t b1[4], b2[4];
                const uint32_t nroff = (uint32_t)(np * 16 * PITCH) * 2 + koff;
                ldsm_x4(b1, b1Base + nroff);
                ldsm_x4(b2, b2Base + nroff);
                #pragma unroll
                for (int mf = 0; mf < 2; mf++) {
                    mma_f16(acc[mf][np * 2 + 0], aq[mf], b1[0], b1[1]);
                    mma_f16(acc[mf][np * 2 + 0], af[mf], b2[0], b2[1]);
                    mma_f16(acc[mf][np * 2 + 1], aq[mf], b1[2], b1[3]);
                    mma_f16(acc[mf][np * 2 + 1], af[mf], b2[2], b2[3]);
                }
            }
        }
    }

    // ---- epilogue: direct float2 stores + t3 ----
    #pragma unroll
    for (int mf = 0; mf < 2; mf++) {
        const int row0 = block_row + wm * 32 + mf * 16 + g;
        #pragma unroll
        for (int nf = 0; nf < 8; nf++) {
            const int col = block_col + wn * 64 + nf * 8 + tg * 2;
            const float t0 = g_t3[col];
            const float t1 = g_t3[col + 1];
            float2 v0 = make_float2(acc[mf][nf][0] + t0, acc[mf][nf][1] + t1);
            float2 v1 = make_float2(acc[mf][nf][2] + t0, acc[mf][nf][3] + t1);
            *reinterpret_cast<float2*>(out + (size_t)row0 * C_DIM + col)       = v0;
            *reinterpret_cast<float2*>(out + (size_t)(row0 + 8) * C_DIM + col) = v1;
        }
    }
}

// ---------------------------------------------------------------------------
extern "C" void kernel_launch(void* const* d_in, const int* in_sizes, int n_in,
                              void* d_out, int out_size) {
    const float* x       = (const float*)d_in[0];   // (8192, 512)
    const float* weight  = (const float*)d_in[1];   // (512, 2048)
    const float* centers = (const float*)d_in[2];   // (2048, 512)
    float* out = (float*)d_out;                     // (8192, 2048)

    cudaFuncSetAttribute(rbf_mma_gemm, cudaFuncAttributeMaxDynamicSharedMemorySize,
                         SMEM_BYTES);

    dim3 pgrid(I_DIM / 32, C_DIM / 32);
    prep_w_kernel<<<pgrid, dim3(32, 8)>>>(weight, centers);
    t3_reduce_kernel<<<(C_DIM + 255) / 256, 256>>>();
    prep_x_kernel<<<(B_DIM * I_DIM / 4) / 256, 256>>>(x);

    dim3 ggrid(C_DIM / BN, B_DIM / BM);   // (16, 64)
    rbf_mma_gemm<<<ggrid, 256, SMEM_BYTES>>>(out);
}